// round 9
// baseline (speedup 1.0000x reference)
#include <cuda_runtime.h>
#include <cstdint>

#define DIM 64
#define KB 4
#define BATCH 16
#define HIN 256
#define WIN 256
#define HO 127
#define WO 127
#define KTOT 1600
#define KC 32
#define CHUNKS 50
#define PER_B (DIM * KTOT)   // 102400

#define AROW 136             // words per row instance; data at [4..131], pads at 3/132
#define NROW 16
#define ABUF (2 * NROW * AROW)        // 4352 words per A buffer
#define BSTRIDE 36
#define BBUF (64 * BSTRIDE)           // 2304 words
#define OFF_B(i) (3 * ABUF + (i) * BBUF)
#define OFF_TAP (3 * ABUF + 3 * BBUF)          // 19968
#define SMEM_WORDS (OFF_TAP + KTOT)            // 21568 words = 86272 B

__device__ float g_xp[BATCH * DIM * 4 * 128 * 128];   // polyphase images (tf32)
__device__ float g_pooled[BATCH * DIM];
__device__ float g_aggb[BATCH * DIM];
__device__ float g_wg[BATCH * DIM * KTOT];            // mixed weights (tf32)
__device__ int   g_taptab[KTOT];
__device__ int   g_rowtab[CHUNKS * NROW];

__device__ __forceinline__ uint32_t smem_u32(const void* p) {
    uint32_t a;
    asm("{ .reg .u64 t; cvta.to.shared.u64 t, %1; cvt.u32.u64 %0, t; }" : "=r"(a) : "l"(p));
    return a;
}
__device__ __forceinline__ float to_tf32(float v) {
    uint32_t u; asm("cvt.rna.tf32.f32 %0, %1;" : "=r"(u) : "f"(v));
    return __uint_as_float(u);
}
__device__ __forceinline__ void mma_tf32(float* d, const uint32_t* a, uint32_t b0, uint32_t b1) {
    asm volatile(
        "mma.sync.aligned.m16n8k8.row.col.f32.tf32.tf32.f32 "
        "{%0,%1,%2,%3}, {%4,%5,%6,%7}, {%8,%9}, {%0,%1,%2,%3};"
        : "+f"(d[0]), "+f"(d[1]), "+f"(d[2]), "+f"(d[3])
        : "r"(a[0]), "r"(a[1]), "r"(a[2]), "r"(a[3]), "r"(b0), "r"(b1));
}
__device__ __forceinline__ void cp16(uint32_t dst, const float* src, int sz) {
    asm volatile("cp.async.ca.shared.global [%0], [%1], 16, %2;"
                 :: "r"(dst), "l"(__cvta_generic_to_global(src)), "r"(sz) : "memory");
}

// ------------------------------------------------- prepass: polyphase split + pool + tables
__global__ void prepass_kernel(const float* __restrict__ x) {
    int bc = blockIdx.x;
    if (bc == 0 && threadIdx.x < CHUNKS) {
        int c = threadIdx.x;
        int keys[NROW];
        int n = 0;
        for (int j = 0; j < KC; j++) {
            int k = c * KC + j;
            int cin = k / 25, t = k % 25, ky = t / 5, kx = t % 5;
            int pr = (ky + 1) & 1, pc = (kx + 1) & 1;
            int ryo = (ky - 1) >> 1, dx = (kx - 1) >> 1;
            int key = ((cin * 4 + pr * 2 + pc) << 8) | (ryo + 1);
            int r = -1;
            for (int i = 0; i < n; i++) if (keys[i] == key) { r = i; break; }
            if (r < 0) { keys[n] = key; r = n++; }
            g_taptab[k] = r * 2 * AROW + 4 + dx;
        }
        for (int i = 0; i < NROW; i++)
            g_rowtab[c * NROW + i] = (i < n) ? keys[i] : 1;
    }
    const float2* src = (const float2*)(x + (size_t)bc * HIN * WIN);
    float* pl = g_xp + (size_t)bc * 4 * 16384;
    float s = 0.f;
    for (int i = threadIdx.x; i < 128 * 256; i += 256) {
        int iy = i >> 7, hx = i & 127;
        float2 v = src[i];
        s += v.x + v.y;
        int r = iy >> 1, pr = iy & 1;
        pl[(pr * 2 + 0) * 16384 + r * 128 + hx] = to_tf32(v.x);
        pl[(pr * 2 + 1) * 16384 + r * 128 + hx] = to_tf32(v.y);
    }
    __shared__ float red[256];
    red[threadIdx.x] = s;
    __syncthreads();
    for (int off = 128; off > 0; off >>= 1) {
        if (threadIdx.x < off) red[threadIdx.x] += red[threadIdx.x + off];
        __syncthreads();
    }
    if (threadIdx.x == 0) g_pooled[bc] = red[0] * (1.f / (HIN * WIN));
}

// ------------------------------------------------- attention + weight mix + w_ret + agg_b
__global__ void aggw_kernel(const float* __restrict__ fc1_w, const float* __restrict__ fc1_b,
                            const float* __restrict__ fc2_w, const float* __restrict__ fc2_b,
                            const float* __restrict__ weight, const float* __restrict__ bias,
                            float* __restrict__ out_wret) {
    __shared__ float s_att[KB];
    int b = blockIdx.y, tid = threadIdx.x;
    if (tid == 0) {
        float a[KB];
        #pragma unroll
        for (int k = 0; k < KB; k++) {
            float s = fc1_b[k];
            for (int c = 0; c < DIM; c++) s += g_pooled[b * DIM + c] * fc1_w[k * DIM + c];
            a[k] = fmaxf(s, 0.f);
        }
        float lg[KB], m = -1e30f;
        #pragma unroll
        for (int j = 0; j < KB; j++) {
            float s = fc2_b[j];
            #pragma unroll
            for (int k = 0; k < KB; k++) s += a[k] * fc2_w[j * KB + k];
            lg[j] = s; m = fmaxf(m, s);
        }
        float den = 0.f;
        #pragma unroll
        for (int j = 0; j < KB; j++) { lg[j] = expf(lg[j] - m); den += lg[j]; }
        float inv = 1.f / den;
        #pragma unroll
        for (int j = 0; j < KB; j++) s_att[j] = lg[j] * inv;
    }
    __syncthreads();
    int r = blockIdx.x * 256 + tid;
    float s = 0.f;
    #pragma unroll
    for (int k = 0; k < KB; k++) s += s_att[k] * weight[(size_t)k * PER_B + r];
    g_wg[(size_t)b * PER_B + r] = to_tf32(s);
    int o = r / KTOT, rem = r - o * KTOT;
    int i = rem / 25, t = rem - i * 25;
    out_wret[((size_t)(b * DIM + o) * 25 + t) * DIM + i] = s;
    if (blockIdx.x == 0 && tid < DIM) {
        float sb = 0.f;
        #pragma unroll
        for (int k = 0; k < KB; k++) sb += s_att[k] * bias[k * DIM + tid];
        g_aggb[b * DIM + tid] = sb;
    }
}

// ------------------------------------------------- tf32 mma.sync implicit-GEMM conv
// CTA=(oy-pair, b): D[256px,64co]. 4 warps, warp tile 64px x 64co.
// 3-stage cp.async ring, 1 sync/chunk, taptab in SMEM.
__global__ __launch_bounds__(128) void conv_mma_kernel(float* __restrict__ out, int b_base) {
    extern __shared__ float sm[];
    int tid = threadIdx.x, lane = tid & 31, wm = tid >> 5;   // 4 warps
    int oy0 = blockIdx.x * 2, b = b_base + blockIdx.y;

    const float* xpb = g_xp + (size_t)b * 4 * DIM * 16384;
    const float* wgb = g_wg + (size_t)b * PER_B;
    int* sT = (int*)(sm + OFF_TAP);

    for (int i = tid; i < KTOT; i += 128) sT[i] = g_taptab[i];

    int j = tid >> 2, u = tid & 3;          // A stage: 32 row instances x 4 threads
    int rr = j >> 1, q = j & 1;
    int bco = tid >> 1, bhalf = tid & 1;    // B stage: 64 co x 2 threads

    float acc[4][8][4];
    #pragma unroll
    for (int mt = 0; mt < 4; mt++)
        #pragma unroll
        for (int nt = 0; nt < 8; nt++)
            #pragma unroll
            for (int r2 = 0; r2 < 4; r2++) acc[mt][nt][r2] = 0.f;

    int g = lane >> 2, cl = lane & 3;
    int qoff = (wm >> 1) * AROW;
    int oxb = (wm & 1) * 64 + g;

    auto stage = [&](int c) {
        int buf = c % 3;
        float* sA = sm + buf * ABUF;
        float* sB = sm + OFF_B(buf);
        int meta = g_rowtab[c * NROW + rr];
        int ry = oy0 + q + ((meta & 15) - 1);
        bool ok = (unsigned)ry < 128u;
        const float* src = xpb + (meta >> 8) * 16384 + ry * 128;
        float* row = sA + j * AROW;
        if (u == 0) row[3] = 0.f;
        if (u == 3) row[132] = 0.f;
        uint32_t dstb = smem_u32(row + 4);
        int sz = ok ? 16 : 0;
        #pragma unroll
        for (int i = 0; i < 8; i++) {
            int idx = u + i * 4;
            cp16(dstb + (uint32_t)idx * 16u, src + idx * 4, sz);
        }
        const float* wsrc = wgb + (size_t)bco * KTOT + c * KC + bhalf * 16;
        uint32_t bdst = smem_u32(sB + bco * BSTRIDE + bhalf * 16);
        #pragma unroll
        for (int i = 0; i < 4; i++) cp16(bdst + (uint32_t)i * 16u, wsrc + i * 4, 16);
    };

    auto consume = [&](int c) {
        int buf = c % 3;
        const float* sA = sm + buf * ABUF;
        const float* sB = sm + OFF_B(buf);
        const int* tb = sT + c * KC;
        #pragma unroll
        for (int k8 = 0; k8 < 4; k8++) {
            int k0 = k8 * 8;
            int off0 = tb[k0 + cl] + qoff + oxb;
            int off4 = tb[k0 + cl + 4] + qoff + oxb;
            uint32_t a[4][4];
            #pragma unroll
            for (int mt = 0; mt < 4; mt++) {
                a[mt][0] = __float_as_uint(sA[off0 + mt * 16]);
                a[mt][1] = __float_as_uint(sA[off0 + mt * 16 + 8]);
                a[mt][2] = __float_as_uint(sA[off4 + mt * 16]);
                a[mt][3] = __float_as_uint(sA[off4 + mt * 16 + 8]);
            }
            #pragma unroll
            for (int nt = 0; nt < 8; nt++) {
                const float* bb = sB + (nt * 8 + g) * BSTRIDE + k0 + cl;
                uint32_t b0 = __float_as_uint(bb[0]);
                uint32_t b1 = __float_as_uint(bb[4]);
                #pragma unroll
                for (int mt = 0; mt < 4; mt++)
                    mma_tf32(acc[mt][nt], a[mt], b0, b1);
            }
        }
    };

    stage(0);
    asm volatile("cp.async.commit_group;" ::: "memory");
    stage(1);
    asm volatile("cp.async.commit_group;" ::: "memory");
    for (int c = 0; c < CHUNKS; c++) {
        if (c + 2 < CHUNKS) {
            asm volatile("cp.async.wait_group 1;" ::: "memory");
            __syncthreads();
            stage(c + 2);
            asm volatile("cp.async.commit_group;" ::: "memory");
        } else {
            asm volatile("cp.async.wait_group 0;" ::: "memory");
            __syncthreads();
        }
        consume(c);
    }

    const float* ab = g_aggb + b * DIM;
    #pragma unroll
    for (int mt = 0; mt < 4; mt++) {
        int pxb = wm * 64 + mt * 16 + g;
        #pragma unroll
        for (int half = 0; half < 2; half++) {
            int px = pxb + half * 8;
            int qq = px >> 7, ox = px & 127;
            int oy = oy0 + qq;
            if (oy < HO && ox < WO) {
                #pragma unroll
                for (int nt = 0; nt < 8; nt++) {
                    int co = nt * 8 + cl * 2;
                    float* op = out + ((size_t)(b * DIM + co)) * (HO * WO) + oy * WO + ox;
                    op[0]       = acc[mt][nt][2 * half]     + ab[co];
                    op[HO * WO] = acc[mt][nt][2 * half + 1] + ab[co + 1];
                }
            }
        }
    }
}

// ------------------------------------------------- launch
extern "C" void kernel_launch(void* const* d_in, const int* in_sizes, int n_in,
                              void* d_out, int out_size) {
    const float* x     = (const float*)d_in[0];
    const float* fc1_w = (const float*)d_in[1];
    const float* fc1_b = (const float*)d_in[2];
    const float* fc2_w = (const float*)d_in[3];
    const float* fc2_b = (const float*)d_in[4];
    const float* weight = (const float*)d_in[5];
    const float* bias  = (const float*)d_in[6];

    float* out = (float*)d_out;
    float* wret = out + (size_t)BATCH * DIM * HO * WO;

    prepass_kernel<<<BATCH * DIM, 256>>>(x);
    aggw_kernel<<<dim3(PER_B / 256, BATCH), 256>>>(fc1_w, fc1_b, fc2_w, fc2_b,
                                                   weight, bias, wret);
    cudaFuncSetAttribute(conv_mma_kernel, cudaFuncAttributeMaxDynamicSharedMemorySize,
                         SMEM_WORDS * 4);
    conv_mma_kernel<<<dim3(64, 8), 128, SMEM_WORDS * 4>>>(out, 0);
    conv_mma_kernel<<<dim3(64, 8), 128, SMEM_WORDS * 4>>>(out, 8);
}

// round 10
// speedup vs baseline: 1.2019x; 1.2019x over previous
#include <cuda_runtime.h>
#include <cstdint>

#define DIM 64
#define KB 4
#define BATCH 16
#define HIN 256
#define WIN 256
#define HO 127
#define WO 127
#define KTOT 1600
#define KC 32
#define CHUNKS 50
#define PER_B (DIM * KTOT)   // 102400

#define AROW 136             // words per row instance; data at [4..131], pads at 3/132
#define NROW 16
#define ABUF (2 * NROW * AROW)        // 4352 words per A stage
#define BSTRIDE 36
#define BBUF (64 * BSTRIDE)           // 2304 words
#define OFF_B(i) (2 * ABUF + (i) * BBUF)
#define OFF_TAP (2 * ABUF + 2 * BBUF)          // 13312
#define SMEM_WORDS (OFF_TAP + KTOT)            // 14912 words = 59648 B -> 3 CTAs/SM

__device__ float g_xp[BATCH * DIM * 4 * 128 * 128];   // polyphase images (tf32)
__device__ float g_pooled[BATCH * DIM];
__device__ float g_aggb[BATCH * DIM];
__device__ float g_wg[BATCH * DIM * KTOT];            // mixed weights (tf32)
__device__ int   g_taptab[KTOT];
__device__ int   g_rowtab[CHUNKS * NROW];

__device__ __forceinline__ uint32_t smem_u32(const void* p) {
    uint32_t a;
    asm("{ .reg .u64 t; cvta.to.shared.u64 t, %1; cvt.u32.u64 %0, t; }" : "=r"(a) : "l"(p));
    return a;
}
__device__ __forceinline__ float to_tf32(float v) {
    uint32_t u; asm("cvt.rna.tf32.f32 %0, %1;" : "=r"(u) : "f"(v));
    return __uint_as_float(u);
}
__device__ __forceinline__ void mma_tf32(float* d, const uint32_t* a, uint32_t b0, uint32_t b1) {
    asm volatile(
        "mma.sync.aligned.m16n8k8.row.col.f32.tf32.tf32.f32 "
        "{%0,%1,%2,%3}, {%4,%5,%6,%7}, {%8,%9}, {%0,%1,%2,%3};"
        : "+f"(d[0]), "+f"(d[1]), "+f"(d[2]), "+f"(d[3])
        : "r"(a[0]), "r"(a[1]), "r"(a[2]), "r"(a[3]), "r"(b0), "r"(b1));
}
__device__ __forceinline__ void cp16(uint32_t dst, const float* src, int sz) {
    asm volatile("cp.async.ca.shared.global [%0], [%1], 16, %2;"
                 :: "r"(dst), "l"(__cvta_generic_to_global(src)), "r"(sz) : "memory");
}

// ------------------------------------------------- prepass: polyphase split + pool + tables
__global__ void prepass_kernel(const float* __restrict__ x) {
    int bc = blockIdx.x;
    if (bc == 0 && threadIdx.x < CHUNKS) {
        int c = threadIdx.x;
        int keys[NROW];
        int n = 0;
        for (int j = 0; j < KC; j++) {
            int k = c * KC + j;
            int cin = k / 25, t = k % 25, ky = t / 5, kx = t % 5;
            int pr = (ky + 1) & 1, pc = (kx + 1) & 1;
            int ryo = (ky - 1) >> 1, dx = (kx - 1) >> 1;
            int key = ((cin * 4 + pr * 2 + pc) << 8) | (ryo + 1);
            int r = -1;
            for (int i = 0; i < n; i++) if (keys[i] == key) { r = i; break; }
            if (r < 0) { keys[n] = key; r = n++; }
            g_taptab[k] = r * 2 * AROW + 4 + dx;
        }
        for (int i = 0; i < NROW; i++)
            g_rowtab[c * NROW + i] = (i < n) ? keys[i] : 1;
    }
    const float2* src = (const float2*)(x + (size_t)bc * HIN * WIN);
    float* pl = g_xp + (size_t)bc * 4 * 16384;
    float s = 0.f;
    for (int i = threadIdx.x; i < 128 * 256; i += 256) {
        int iy = i >> 7, hx = i & 127;
        float2 v = src[i];
        s += v.x + v.y;
        int r = iy >> 1, pr = iy & 1;
        pl[(pr * 2 + 0) * 16384 + r * 128 + hx] = to_tf32(v.x);
        pl[(pr * 2 + 1) * 16384 + r * 128 + hx] = to_tf32(v.y);
    }
    __shared__ float red[256];
    red[threadIdx.x] = s;
    __syncthreads();
    for (int off = 128; off > 0; off >>= 1) {
        if (threadIdx.x < off) red[threadIdx.x] += red[threadIdx.x + off];
        __syncthreads();
    }
    if (threadIdx.x == 0) g_pooled[bc] = red[0] * (1.f / (HIN * WIN));
}

// ------------------------------------------------- attention + weight mix + w_ret + agg_b
__global__ void aggw_kernel(const float* __restrict__ fc1_w, const float* __restrict__ fc1_b,
                            const float* __restrict__ fc2_w, const float* __restrict__ fc2_b,
                            const float* __restrict__ weight, const float* __restrict__ bias,
                            float* __restrict__ out_wret) {
    __shared__ float s_att[KB];
    int b = blockIdx.y, tid = threadIdx.x;
    if (tid == 0) {
        float a[KB];
        #pragma unroll
        for (int k = 0; k < KB; k++) {
            float s = fc1_b[k];
            for (int c = 0; c < DIM; c++) s += g_pooled[b * DIM + c] * fc1_w[k * DIM + c];
            a[k] = fmaxf(s, 0.f);
        }
        float lg[KB], m = -1e30f;
        #pragma unroll
        for (int j = 0; j < KB; j++) {
            float s = fc2_b[j];
            #pragma unroll
            for (int k = 0; k < KB; k++) s += a[k] * fc2_w[j * KB + k];
            lg[j] = s; m = fmaxf(m, s);
        }
        float den = 0.f;
        #pragma unroll
        for (int j = 0; j < KB; j++) { lg[j] = expf(lg[j] - m); den += lg[j]; }
        float inv = 1.f / den;
        #pragma unroll
        for (int j = 0; j < KB; j++) s_att[j] = lg[j] * inv;
    }
    __syncthreads();
    int r = blockIdx.x * 256 + tid;
    float s = 0.f;
    #pragma unroll
    for (int k = 0; k < KB; k++) s += s_att[k] * weight[(size_t)k * PER_B + r];
    g_wg[(size_t)b * PER_B + r] = to_tf32(s);
    int o = r / KTOT, rem = r - o * KTOT;
    int i = rem / 25, t = rem - i * 25;
    out_wret[((size_t)(b * DIM + o) * 25 + t) * DIM + i] = s;
    if (blockIdx.x == 0 && tid < DIM) {
        float sb = 0.f;
        #pragma unroll
        for (int k = 0; k < KB; k++) sb += s_att[k] * bias[k * DIM + tid];
        g_aggb[b * DIM + tid] = sb;
    }
}

// ------------------------------------------------- tf32 mma.sync implicit-GEMM conv
// CTA=(oy-pair, b): D[256px,64co]. 4 warps, warp tile 64px x 64co.
// 2-stage cp.async ring (59.6 KB smem -> 3 CTAs/SM = 12 warps/SM).
__global__ __launch_bounds__(128, 3) void conv_mma_kernel(float* __restrict__ out) {
    extern __shared__ float sm[];
    int tid = threadIdx.x, lane = tid & 31, wm = tid >> 5;   // 4 warps
    int oy0 = blockIdx.x * 2, b = blockIdx.y;

    const float* xpb = g_xp + (size_t)b * 4 * DIM * 16384;
    const float* wgb = g_wg + (size_t)b * PER_B;
    int* sT = (int*)(sm + OFF_TAP);

    for (int i = tid; i < KTOT; i += 128) sT[i] = g_taptab[i];

    int j = tid >> 2, u = tid & 3;          // A stage: 32 row instances x 4 threads
    int rr = j >> 1, q = j & 1;
    int bco = tid >> 1, bhalf = tid & 1;    // B stage: 64 co x 2 threads

    float acc[4][8][4];
    #pragma unroll
    for (int mt = 0; mt < 4; mt++)
        #pragma unroll
        for (int nt = 0; nt < 8; nt++)
            #pragma unroll
            for (int r2 = 0; r2 < 4; r2++) acc[mt][nt][r2] = 0.f;

    int g = lane >> 2, cl = lane & 3;
    int qoff = (wm >> 1) * AROW;
    int oxb = (wm & 1) * 64 + g;

    auto stage = [&](int c) {
        int buf = c & 1;
        float* sA = sm + buf * ABUF;
        float* sB = sm + OFF_B(buf);
        int meta = g_rowtab[c * NROW + rr];
        int ry = oy0 + q + ((meta & 15) - 1);
        bool ok = (unsigned)ry < 128u;
        const float* src = xpb + (meta >> 8) * 16384 + ry * 128;
        float* row = sA + j * AROW;
        if (u == 0) row[3] = 0.f;
        if (u == 3) row[132] = 0.f;
        uint32_t dstb = smem_u32(row + 4);
        int sz = ok ? 16 : 0;
        #pragma unroll
        for (int i = 0; i < 8; i++) {
            int idx = u + i * 4;
            cp16(dstb + (uint32_t)idx * 16u, src + idx * 4, sz);
        }
        const float* wsrc = wgb + (size_t)bco * KTOT + c * KC + bhalf * 16;
        uint32_t bdst = smem_u32(sB + bco * BSTRIDE + bhalf * 16);
        #pragma unroll
        for (int i = 0; i < 4; i++) cp16(bdst + (uint32_t)i * 16u, wsrc + i * 4, 16);
    };

    auto consume = [&](int c) {
        int buf = c & 1;
        const float* sA = sm + buf * ABUF;
        const float* sB = sm + OFF_B(buf);
        const int* tb = sT + c * KC;
        #pragma unroll
        for (int k8 = 0; k8 < 4; k8++) {
            int k0 = k8 * 8;
            int off0 = tb[k0 + cl] + qoff + oxb;
            int off4 = tb[k0 + cl + 4] + qoff + oxb;
            uint32_t a[4][4];
            #pragma unroll
            for (int mt = 0; mt < 4; mt++) {
                a[mt][0] = __float_as_uint(sA[off0 + mt * 16]);
                a[mt][1] = __float_as_uint(sA[off0 + mt * 16 + 8]);
                a[mt][2] = __float_as_uint(sA[off4 + mt * 16]);
                a[mt][3] = __float_as_uint(sA[off4 + mt * 16 + 8]);
            }
            #pragma unroll
            for (int nt = 0; nt < 8; nt++) {
                const float* bb = sB + (nt * 8 + g) * BSTRIDE + k0 + cl;
                uint32_t b0 = __float_as_uint(bb[0]);
                uint32_t b1 = __float_as_uint(bb[4]);
                #pragma unroll
                for (int mt = 0; mt < 4; mt++)
                    mma_tf32(acc[mt][nt], a[mt], b0, b1);
            }
        }
    };

    stage(0);
    asm volatile("cp.async.commit_group;" ::: "memory");
    for (int c = 0; c < CHUNKS; c++) {
        if (c + 1 < CHUNKS) {
            stage(c + 1);
            asm volatile("cp.async.commit_group;" ::: "memory");
            asm volatile("cp.async.wait_group 1;" ::: "memory");
        } else {
            asm volatile("cp.async.wait_group 0;" ::: "memory");
        }
        __syncthreads();          // buffer c fully staged, visible to all warps
        consume(c);
        __syncthreads();          // all warps done reading buf c before staging c+2 into it
    }

    const float* ab = g_aggb + b * DIM;
    #pragma unroll
    for (int mt = 0; mt < 4; mt++) {
        int pxb = wm * 64 + mt * 16 + g;
        #pragma unroll
        for (int half = 0; half < 2; half++) {
            int px = pxb + half * 8;
            int qq = px >> 7, ox = px & 127;
            int oy = oy0 + qq;
            if (oy < HO && ox < WO) {
                #pragma unroll
                for (int nt = 0; nt < 8; nt++) {
                    int co = nt * 8 + cl * 2;
                    float* op = out + ((size_t)(b * DIM + co)) * (HO * WO) + oy * WO + ox;
                    op[0]       = acc[mt][nt][2 * half]     + ab[co];
                    op[HO * WO] = acc[mt][nt][2 * half + 1] + ab[co + 1];
                }
            }
        }
    }
}

// ------------------------------------------------- launch
extern "C" void kernel_launch(void* const* d_in, const int* in_sizes, int n_in,
                              void* d_out, int out_size) {
    const float* x     = (const float*)d_in[0];
    const float* fc1_w = (const float*)d_in[1];
    const float* fc1_b = (const float*)d_in[2];
    const float* fc2_w = (const float*)d_in[3];
    const float* fc2_b = (const float*)d_in[4];
    const float* weight = (const float*)d_in[5];
    const float* bias  = (const float*)d_in[6];

    float* out = (float*)d_out;
    float* wret = out + (size_t)BATCH * DIM * HO * WO;

    prepass_kernel<<<BATCH * DIM, 256>>>(x);
    aggw_kernel<<<dim3(PER_B / 256, BATCH), 256>>>(fc1_w, fc1_b, fc2_w, fc2_b,
                                                   weight, bias, wret);
    cudaFuncSetAttribute(conv_mma_kernel, cudaFuncAttributeMaxDynamicSharedMemorySize,
                         SMEM_WORDS * 4);
    conv_mma_kernel<<<dim3(64, BATCH), 128, SMEM_WORDS * 4>>>(out);
}